// round 3
// baseline (speedup 1.0000x reference)
#include <cuda_runtime.h>
#include <math.h>

#define BB   8
#define NPOS 4096
#define CC   512
#define NH   8
#define DH   64
#define KDIM 512

// ---------------- scratch (device globals; no allocs) ----------------
__device__ float g_qfeat[BB * NPOS * CC];
__device__ float g_qrope[BB * NPOS * CC];
__device__ float g_kfeat[BB * NPOS * CC];
__device__ float g_krope[BB * NPOS * CC];
__device__ float g_ksum_part[BB * 16 * CC];
__device__ float g_ksum[BB * CC];
__device__ float g_kv_part[8 * BB * NH * DH * DH];
__device__ float g_kv[BB * NH * DH * DH];

__device__ __forceinline__ void fma2(unsigned long long& acc,
                                     unsigned long long a,
                                     unsigned long long b) {
    asm("fma.rn.f32x2 %0, %1, %2, %0;" : "+l"(acc) : "l"(a), "l"(b));
}
__device__ __forceinline__ float lo32(unsigned long long v) {
    return __uint_as_float((unsigned)(v & 0xffffffffull));
}
__device__ __forceinline__ float hi32(unsigned long long v) {
    return __uint_as_float((unsigned)(v >> 32));
}

// ============================================================================
// K1: qk = x @ Wqk^T + bqk, fused elu+1 and RoPE epilogue.
// M=32768 (b*n), N=1024, K=512. Tiles BM=128, BN=128, BK=16, 256 threads,
// per-thread 8x8 via packed f32x2 FMA (A duplicated in smem, B pairs natural).
// ============================================================================
__global__ __launch_bounds__(256) void k_gemm_qk(const float* __restrict__ x,
                                                 const float* __restrict__ Wqk,
                                                 const float* __restrict__ bqk) {
    __shared__ float As2[16 * 264];  // duplicated A: As2[k][2m]=As2[k][2m+1]=A[m][k]
    __shared__ float Bs[16 * 132];   // Bs[k][j]

    const int tid  = threadIdx.x;
    const int bcol = blockIdx.x;   // 0..7   (N tiles)
    const int brow = blockIdx.y;   // 0..255 (M tiles)
    const int trow = tid >> 4;     // 0..15
    const int tcol = tid & 15;     // 0..15

    const int m00 = brow * 128;
    const int j00 = bcol * 128;

    unsigned long long acc[8][4];
#pragma unroll
    for (int i = 0; i < 8; i++)
#pragma unroll
        for (int j = 0; j < 4; j++) acc[i][j] = 0ull;

    for (int t = 0; t < KDIM / 16; ++t) {
        const int k0 = t * 16;
#pragma unroll
        for (int i = 0; i < 2; i++) {
            int f   = tid + i * 256;
            int row = f >> 2;      // 0..127
            int c4  = f & 3;       // 0..3
            float4 va = *(const float4*)(x + (size_t)(m00 + row) * KDIM + k0 + c4 * 4);
            float4 vb = *(const float4*)(Wqk + (size_t)(j00 + row) * KDIM + k0 + c4 * 4);
            int kb = c4 * 4;
            As2[(kb + 0) * 264 + 2 * row]     = va.x;
            As2[(kb + 0) * 264 + 2 * row + 1] = va.x;
            As2[(kb + 1) * 264 + 2 * row]     = va.y;
            As2[(kb + 1) * 264 + 2 * row + 1] = va.y;
            As2[(kb + 2) * 264 + 2 * row]     = va.z;
            As2[(kb + 2) * 264 + 2 * row + 1] = va.z;
            As2[(kb + 3) * 264 + 2 * row]     = va.w;
            As2[(kb + 3) * 264 + 2 * row + 1] = va.w;
            Bs[(kb + 0) * 132 + row] = vb.x;
            Bs[(kb + 1) * 132 + row] = vb.y;
            Bs[(kb + 2) * 132 + row] = vb.z;
            Bs[(kb + 3) * 132 + row] = vb.w;
        }
        __syncthreads();
#pragma unroll
        for (int kk = 0; kk < 16; ++kk) {
            const float* ap = &As2[kk * 264 + trow * 16];
            const float* bp = &Bs[kk * 132 + tcol * 8];
            ulonglong2 a01 = *(const ulonglong2*)(ap);
            ulonglong2 a23 = *(const ulonglong2*)(ap + 4);
            ulonglong2 a45 = *(const ulonglong2*)(ap + 8);
            ulonglong2 a67 = *(const ulonglong2*)(ap + 12);
            ulonglong2 b01 = *(const ulonglong2*)(bp);
            ulonglong2 b23 = *(const ulonglong2*)(bp + 4);
            unsigned long long aa[8] = {a01.x, a01.y, a23.x, a23.y,
                                        a45.x, a45.y, a67.x, a67.y};
            unsigned long long bb2[4] = {b01.x, b01.y, b23.x, b23.y};
#pragma unroll
            for (int i = 0; i < 8; i++)
#pragma unroll
                for (int j = 0; j < 4; j++) fma2(acc[i][j], aa[i], bb2[j]);
        }
        __syncthreads();
    }

    // ---------------- epilogue: bias, elu+1, RoPE, store ----------------
    const bool is_k = (j00 >= CC);
    const int  jc0  = (is_k ? j00 - CC : j00) + tcol * 8;  // channel within q or k half
    float theta[4];
#pragma unroll
    for (int p = 0; p < 4; p++) {
        int j2 = (jc0 >> 1) + p;   // pair index 0..255
        int jm = j2 & 127;
        theta[p] = exp2f(-(float)jm * (13.287712379549449f / 128.0f));  // 10000^(-jm/128)
    }
    float bload[8];
#pragma unroll
    for (int jj = 0; jj < 8; jj++) bload[jj] = bqk[j00 + tcol * 8 + jj];

#pragma unroll
    for (int i = 0; i < 8; i++) {
        int m = m00 + trow * 8 + i;
        int n = m & (NPOS - 1);
        float hi_f = (float)(n >> 6);
        float wi_f = (float)(n & 63);
        float f[8];
#pragma unroll
        for (int jj = 0; jj < 8; jj++) {
            int jp  = jj >> 1;
            float v = ((jj & 1) ? hi32(acc[i][jp]) : lo32(acc[i][jp])) + bload[jj];
            f[jj]   = (v > 0.f) ? (v + 1.f) : expf(v);  // elu(v)+1
        }
        float outr[8];
#pragma unroll
        for (int p = 0; p < 4; p++) {
            int   j2  = (jc0 >> 1) + p;
            float pos = (j2 < 128) ? hi_f : wi_f;
            float ang = pos * theta[p];
            float s, c;
            sincosf(ang, &s, &c);
            float re = f[2 * p], im = f[2 * p + 1];
            outr[2 * p]     = c * re - s * im;
            outr[2 * p + 1] = c * im + s * re;
        }
        size_t base = (size_t)m * CC + jc0;
        if (is_k) {
            *(float4*)&g_krope[base]     = *(float4*)&outr[0];
            *(float4*)&g_krope[base + 4] = *(float4*)&outr[4];
            *(float4*)&g_kfeat[base]     = *(float4*)&f[0];
            *(float4*)&g_kfeat[base + 4] = *(float4*)&f[4];
        } else {
            *(float4*)&g_qrope[base]     = *(float4*)&outr[0];
            *(float4*)&g_qrope[base + 4] = *(float4*)&outr[4];
            *(float4*)&g_qfeat[base]     = *(float4*)&f[0];
            *(float4*)&g_qfeat[base + 4] = *(float4*)&f[4];
        }
    }
}

// ============================================================================
// K1b/K1c: deterministic two-stage ksum (for kmean)
// ============================================================================
__global__ void k_ksum_part() {
    int b  = blockIdx.y;      // 0..7
    int cx = blockIdx.x;      // 0..15
    int ch = threadIdx.x;     // 0..511
    const float* p = g_kfeat + ((size_t)b * NPOS + cx * 256) * CC + ch;
    float s = 0.f;
    for (int i = 0; i < 256; i++) s += p[(size_t)i * CC];
    g_ksum_part[(b * 16 + cx) * CC + ch] = s;
}

__global__ void k_ksum_final() {
    int idx = blockIdx.x * 256 + threadIdx.x;  // 0..4095
    if (idx < BB * CC) {
        int b = idx >> 9, ch = idx & 511;
        float s = 0.f;
        for (int i = 0; i < 16; i++) s += g_ksum_part[(b * 16 + i) * CC + ch];
        g_ksum[idx] = s;
    }
}

// ============================================================================
// K2: kv partials: per (b,head,chunk): 64x64 += k_rope[n,:]^T v[n,:] over 512 n
// ============================================================================
__global__ __launch_bounds__(256) void k_kv_part(const float* __restrict__ x) {
    __shared__ float ks[16 * 64];
    __shared__ float vs[16 * 64];
    int chunk = blockIdx.x;   // 0..7
    int bh    = blockIdx.y;   // 0..63
    int b  = bh >> 3, hh = bh & 7;
    int tid = threadIdx.x;
    int ty = tid >> 4, tx = tid & 15;
    int r = tid >> 4, c4 = tid & 15;   // load mapping: 16 rows x 16 float4

    float acc[4][4] = {};
    for (int it = 0; it < 32; ++it) {
        int n0 = chunk * 512 + it * 16;
        size_t gro = ((size_t)b * NPOS + n0 + r) * CC + hh * DH + c4 * 4;
        *(float4*)&ks[r * 64 + c4 * 4] = *(const float4*)(g_krope + gro);
        *(float4*)&vs[r * 64 + c4 * 4] = *(const float4*)(x + gro);
        __syncthreads();
#pragma unroll
        for (int nn = 0; nn < 16; nn++) {
            float4 a  = *(const float4*)&ks[nn * 64 + ty * 4];
            float4 bv = *(const float4*)&vs[nn * 64 + tx * 4];
            float av[4]  = {a.x, a.y, a.z, a.w};
            float bb2[4] = {bv.x, bv.y, bv.z, bv.w};
#pragma unroll
            for (int i = 0; i < 4; i++)
#pragma unroll
                for (int j = 0; j < 4; j++) acc[i][j] += av[i] * bb2[j];
        }
        __syncthreads();
    }
    float* dst = g_kv_part + ((size_t)chunk * 64 + bh) * DH * DH;
#pragma unroll
    for (int i = 0; i < 4; i++)
#pragma unroll
        for (int j = 0; j < 4; j++)
            dst[(ty * 4 + i) * DH + tx * 4 + j] = acc[i][j];
}

__global__ void k_kv_final() {
    int idx = blockIdx.x * 256 + threadIdx.x;  // 0..262143  (bh*4096 + d*64 + e)
    float s = 0.f;
    for (int c2 = 0; c2 < 8; c2++) s += g_kv_part[(size_t)c2 * 64 * DH * DH + idx];
    g_kv[idx] = s * (1.0f / (float)NPOS);
}

// ============================================================================
// K3: out = (q_rope @ kv) * z + LePE(x); one block per (image row, head, b)
// ============================================================================
__global__ __launch_bounds__(256) void k_out(const float* __restrict__ x,
                                             const float* __restrict__ lepe_w,
                                             const float* __restrict__ lepe_b,
                                             float* __restrict__ out) {
    __shared__ float s_kv[64 * 68];   // phase A: qfeat tile; phase B: kv[d][e]
    __shared__ float s_qrT[64 * 68];  // q_rope transposed: [dd][r]
    __shared__ float s_z[64];
    __shared__ float s_km[64];

    int ntile = blockIdx.x;   // 0..63  == image row hi
    int hh    = blockIdx.y;   // 0..7
    int b     = blockIdx.z;   // 0..7
    int tid   = threadIdx.x;
    int n0    = ntile * 64;

    // Phase A: load qfeat tile into s_kv buffer, load kmean
#pragma unroll
    for (int i = 0; i < 4; i++) {
        int f = tid + i * 256;
        int r = f >> 4, c4 = f & 15;
        float4 v = *(const float4*)(g_qfeat + ((size_t)b * NPOS + n0 + r) * CC + hh * DH + c4 * 4);
        *(float4*)&s_kv[r * 68 + c4 * 4] = v;
    }
    if (tid < 64) s_km[tid] = g_ksum[b * CC + hh * DH + tid] * (1.0f / (float)NPOS);
    __syncthreads();

    if (tid < 64) {
        float dot = 0.f;
#pragma unroll
        for (int dd = 0; dd < 64; dd++) dot += s_kv[tid * 68 + dd] * s_km[dd];
        s_z[tid] = 1.0f / (dot + 1e-6f);
    }
    __syncthreads();

    // Phase B: load kv and transposed q_rope
#pragma unroll
    for (int i = 0; i < 4; i++) {
        int f = tid + i * 256;
        int r = f >> 4, c4 = f & 15;
        *(float4*)&s_kv[r * 68 + c4 * 4] =
            *(const float4*)(g_kv + ((size_t)(b * NH + hh)) * DH * DH + r * DH + c4 * 4);
        float4 v = *(const float4*)(g_qrope + ((size_t)b * NPOS + n0 + r) * CC + hh * DH + c4 * 4);
        s_qrT[(c4 * 4 + 0) * 68 + r] = v.x;
        s_qrT[(c4 * 4 + 1) * 68 + r] = v.y;
        s_qrT[(c4 * 4 + 2) * 68 + r] = v.z;
        s_qrT[(c4 * 4 + 3) * 68 + r] = v.w;
    }
    __syncthreads();

    int ty = tid >> 4, tx = tid & 15;
    int r0 = ty * 4, e0 = tx * 4;
    float acc[4][4] = {};
#pragma unroll
    for (int dd = 0; dd < 64; dd++) {
        float4 a  = *(const float4*)&s_qrT[dd * 68 + r0];
        float4 bv = *(const float4*)&s_kv[dd * 68 + e0];
        float av[4]  = {a.x, a.y, a.z, a.w};
        float bb2[4] = {bv.x, bv.y, bv.z, bv.w};
#pragma unroll
        for (int i = 0; i < 4; i++)
#pragma unroll
            for (int j = 0; j < 4; j++) acc[i][j] += av[i] * bb2[j];
    }

    // Epilogue: z scaling + depthwise 3x3 conv (LePE) + write
    const int hi = ntile;
    float wloc[4][9], bloc[4];
#pragma unroll
    for (int j = 0; j < 4; j++) {
        int ch = hh * DH + e0 + j;
        bloc[j] = lepe_b[ch];
#pragma unroll
        for (int q = 0; q < 9; q++) wloc[j][q] = lepe_w[ch * 9 + q];
    }
#pragma unroll
    for (int ri = 0; ri < 4; ri++) {
        int r  = r0 + ri;
        int wi = r;            // 64 rows == one full image row
        int nn = n0 + r;
        float z = s_z[r];
#pragma unroll
        for (int j = 0; j < 4; j++) {
            int ch = hh * DH + e0 + j;
            float pe = bloc[j];
#pragma unroll
            for (int dy = -1; dy <= 1; dy++) {
                int y = hi + dy;
                if ((unsigned)y < 64u) {
#pragma unroll
                    for (int dx = -1; dx <= 1; dx++) {
                        int xw = wi + dx;
                        if ((unsigned)xw < 64u)
                            pe += wloc[j][(dy + 1) * 3 + dx + 1] *
                                  x[((size_t)b * NPOS + y * 64 + xw) * CC + ch];
                    }
                }
            }
            out[((size_t)b * NPOS + nn) * CC + ch] = acc[ri][j] * z + pe;
        }
    }
}

// ============================================================================
extern "C" void kernel_launch(void* const* d_in, const int* in_sizes, int n_in,
                              void* d_out, int out_size) {
    const float *x = nullptr, *Wqk = nullptr, *bqk = nullptr;
    const float *lw = nullptr, *lb = nullptr;
    for (int i = 0; i < n_in; i++) {
        switch (in_sizes[i]) {
            case BB * NPOS * CC: x   = (const float*)d_in[i]; break;  // 16777216
            case 2 * CC * CC:    Wqk = (const float*)d_in[i]; break;  // 524288
            case 2 * CC:         bqk = (const float*)d_in[i]; break;  // 1024
            case CC * 9:         lw  = (const float*)d_in[i]; break;  // 4608
            case CC:             lb  = (const float*)d_in[i]; break;  // 512
            default: break;                                            // h, w scalars
        }
    }
    float* out = (float*)d_out;

    k_gemm_qk<<<dim3(8, 256), 256>>>(x, Wqk, bqk);
    k_ksum_part<<<dim3(16, 8), 512>>>();
    k_ksum_final<<<16, 256>>>();
    k_kv_part<<<dim3(8, 64), 256>>>(x);
    k_kv_final<<<1024, 256>>>();
    k_out<<<dim3(64, 8, 8), 256>>>(x, lw, lb, out);
}

// round 6
// speedup vs baseline: 1.8988x; 1.8988x over previous
#include <cuda_runtime.h>
#include <cuda_fp16.h>
#include <math.h>
#include <stdint.h>

#define BB   8
#define NPOS 4096
#define CC   512
#define NH   8
#define DH   64
#define KDIM 512
#define MTOT (BB * NPOS)   /* 32768 */
#define NTOT (2 * CC)      /* 1024  */

// ---------------- scratch (device globals; no allocs) ----------------
__device__ float g_qfeat[BB * NPOS * CC];
__device__ float g_qrope[BB * NPOS * CC];
__device__ float g_kfeat[BB * NPOS * CC];
__device__ float g_krope[BB * NPOS * CC];
__device__ float g_ksum_part[BB * 16 * CC];
__device__ float g_ksum[BB * CC];
__device__ float g_kv_part[8 * BB * NH * DH * DH];
__device__ float g_kv[BB * NH * DH * DH];
// fp16 hi/lo planes, row-major [row][512]
__device__ unsigned short g_xh[(size_t)MTOT * KDIM];
__device__ unsigned short g_xl[(size_t)MTOT * KDIM];
__device__ unsigned short g_wh[(size_t)NTOT * KDIM];
__device__ unsigned short g_wl[(size_t)NTOT * KDIM];

// ---------------- PTX helpers (sm_80-era only; no 'a'-gated features) -------
__device__ __forceinline__ uint32_t smem_u32(const void* p) {
    uint32_t a;
    asm("{ .reg .u64 t; cvta.to.shared.u64 t, %1; cvt.u32.u64 %0, t; }"
        : "=r"(a) : "l"(p));
    return a;
}
__device__ __forceinline__ void cpa16(uint32_t dst, const void* src) {
    asm volatile("cp.async.cg.shared.global [%0], [%1], 16;" ::"r"(dst), "l"(src));
}
#define CP_COMMIT() asm volatile("cp.async.commit_group;" ::: "memory")
#define CP_WAIT(n)  asm volatile("cp.async.wait_group %0;" ::"n"(n) : "memory")

__device__ __forceinline__ void ldmx4(uint32_t* r, uint32_t addr) {
    asm volatile("ldmatrix.sync.aligned.m8n8.x4.shared.b16 {%0,%1,%2,%3}, [%4];"
                 : "=r"(r[0]), "=r"(r[1]), "=r"(r[2]), "=r"(r[3]) : "r"(addr));
}
__device__ __forceinline__ void mma16816(float* d, const uint32_t* a,
                                         const uint32_t* b) {
    asm volatile(
        "mma.sync.aligned.m16n8k16.row.col.f32.f16.f16.f32 "
        "{%0,%1,%2,%3}, {%4,%5,%6,%7}, {%8,%9}, {%0,%1,%2,%3};"
        : "+f"(d[0]), "+f"(d[1]), "+f"(d[2]), "+f"(d[3])
        : "r"(a[0]), "r"(a[1]), "r"(a[2]), "r"(a[3]), "r"(b[0]), "r"(b[1]));
}

// ============================================================================
// K0: fp32 -> fp16 hi/lo planes
// ============================================================================
__global__ __launch_bounds__(256) void k_convert(const float* __restrict__ src,
                                                 int sel, int nrow) {
    int idx = blockIdx.x * 256 + threadIdx.x;
    if (idx >= nrow * 128) return;
    int row = idx >> 7;
    int q4  = idx & 127;
    float4 v = *(const float4*)(src + (size_t)row * KDIM + q4 * 4);
    float vv[4] = {v.x, v.y, v.z, v.w};
    unsigned short h[4], l[4];
#pragma unroll
    for (int t = 0; t < 4; t++) {
        __half hb = __float2half_rn(vv[t]);
        __half lb = __float2half_rn(vv[t] - __half2float(hb));
        h[t] = __half_as_ushort(hb);
        l[t] = __half_as_ushort(lb);
    }
    uint2 hp, lp;
    hp.x = (uint32_t)h[1] << 16 | h[0];
    hp.y = (uint32_t)h[3] << 16 | h[2];
    lp.x = (uint32_t)l[1] << 16 | l[0];
    lp.y = (uint32_t)l[3] << 16 | l[2];
    unsigned short* dh = sel ? g_wh : g_xh;
    unsigned short* dl = sel ? g_wl : g_xl;
    size_t base = (size_t)row * KDIM + q4 * 4;
    *(uint2*)(dh + base) = hp;
    *(uint2*)(dl + base) = lp;
}

// ============================================================================
// K1: HMMA (mma.sync m16n8k16 f16) split GEMM  qk = x @ Wqk^T
//     + fused bias, elu+1, RoPE epilogue (register-resident).
// Tiles: BM=128, BN=128, BK=32; 256 thr; warp tile 64x32; cp.async 2-stage.
// SMEM stage: 4 planes (Ah, Al, Bh, Bl), 128 rows x 80B pitch (64B data).
// ============================================================================
#define STG_BYTES 40960          /* 4 planes * 128 * 80 */
#define PLN_BYTES 10240

__global__ __launch_bounds__(256) void k_gemm_mma(const float* __restrict__ bqk) {
    extern __shared__ char dsm[];
    const uint32_t smem0 = smem_u32(dsm);

    const int tid = threadIdx.x;
    const int wid = tid >> 5, lid = tid & 31;
    const int j00 = blockIdx.x * 128;
    const int m00 = blockIdx.y * 128;
    const int warp_m = (wid >> 2) * 64;
    const int n0     = (wid & 3) * 32;

    // --------- cp.async stage loader: 2048 x 16B chunks ----------
    auto load_stage = [&](int it, int s) {
        const uint32_t sb = smem0 + s * STG_BYTES;
        const int k0 = it * 32;
#pragma unroll
        for (int j = 0; j < 8; j++) {
            int id = tid + j * 256;
            int mp = id >> 9;           // 0=Ah 1=Al 2=Bh 3=Bl
            int r  = (id >> 2) & 127;
            int c  = id & 3;
            const unsigned short* src;
            if (mp == 0)      src = g_xh + (size_t)(m00 + r) * KDIM + k0 + c * 8;
            else if (mp == 1) src = g_xl + (size_t)(m00 + r) * KDIM + k0 + c * 8;
            else if (mp == 2) src = g_wh + (size_t)(j00 + r) * KDIM + k0 + c * 8;
            else              src = g_wl + (size_t)(j00 + r) * KDIM + k0 + c * 8;
            cpa16(sb + mp * PLN_BYTES + r * 80 + c * 16, src);
        }
    };

    float acc[4][4][4] = {};

    // ldmatrix per-lane address components (row part precomputed)
    const int a_r  = (lid & 15);               // A row within frag
    const int a_c  = (lid >> 4);               // A c16 base (0/1)
    const int b_r  = (lid & 7) + ((lid >> 4) << 3);  // B row within n16
    const int b_c  = (lid >> 3) & 1;           // B c16 base

    load_stage(0, 0);
    CP_COMMIT();

    for (int it = 0; it < 16; ++it) {
        if (it < 15) {
            load_stage(it + 1, (it + 1) & 1);
            CP_COMMIT();
            CP_WAIT(1);
        } else {
            CP_WAIT(0);
        }
        __syncthreads();

        const uint32_t sb = smem0 + (it & 1) * STG_BYTES;
        const uint32_t ah_b = sb;
        const uint32_t al_b = sb + PLN_BYTES;
        const uint32_t bh_b = sb + 2 * PLN_BYTES;
        const uint32_t bl_b = sb + 3 * PLN_BYTES;

#pragma unroll
        for (int ks = 0; ks < 2; ++ks) {
            uint32_t ah[4][4], al[4][4], bh[4][2], bl[4][2];
#pragma unroll
            for (int mf = 0; mf < 4; mf++) {
                uint32_t off = (uint32_t)(warp_m + mf * 16 + a_r) * 80 +
                               (a_c + ks * 2) * 16;
                ldmx4(ah[mf], ah_b + off);
                ldmx4(al[mf], al_b + off);
            }
#pragma unroll
            for (int nf2 = 0; nf2 < 2; nf2++) {
                uint32_t off = (uint32_t)(n0 + nf2 * 16 + b_r) * 80 +
                               (b_c + ks * 2) * 16;
                uint32_t t[4];
                ldmx4(t, bh_b + off);
                bh[nf2 * 2][0] = t[0]; bh[nf2 * 2][1] = t[1];
                bh[nf2 * 2 + 1][0] = t[2]; bh[nf2 * 2 + 1][1] = t[3];
                ldmx4(t, bl_b + off);
                bl[nf2 * 2][0] = t[0]; bl[nf2 * 2][1] = t[1];
                bl[nf2 * 2 + 1][0] = t[2]; bl[nf2 * 2 + 1][1] = t[3];
            }
#pragma unroll
            for (int mf = 0; mf < 4; mf++)
#pragma unroll
                for (int nf = 0; nf < 4; nf++) {
                    mma16816(acc[mf][nf], ah[mf], bh[nf]);
                    mma16816(acc[mf][nf], al[mf], bh[nf]);
                    mma16816(acc[mf][nf], ah[mf], bl[nf]);
                }
        }
        __syncthreads();
    }

    // --------- epilogue: bias, elu+1, RoPE, direct float2 stores ----------
    const bool is_k = (j00 >= CC);
    const int  jb   = (is_k ? j00 - CC : j00) + n0 + 2 * (lid & 3);
    float th[4], bx[4], by[4];
    bool  uh[4];
#pragma unroll
    for (int nf = 0; nf < 4; nf++) {
        int jch = jb + nf * 8;
        int j2  = jch >> 1;
        int jm  = j2 & 127;
        th[nf] = exp2f(-(float)jm * (13.287712379549449f / 128.0f));
        uh[nf] = (j2 < 128);
        float2 bv = *(const float2*)(bqk + j00 + n0 + nf * 8 + 2 * (lid & 3));
        bx[nf] = bv.x;
        by[nf] = bv.y;
    }
    float* feat = is_k ? g_kfeat : g_qfeat;
    float* rope = is_k ? g_krope : g_qrope;

#pragma unroll
    for (int mf = 0; mf < 4; mf++) {
        int rbase = m00 + warp_m + mf * 16 + (lid >> 2);
#pragma unroll
        for (int ri = 0; ri < 2; ri++) {
            int   r  = rbase + ri * 8;
            int   n  = r & (NPOS - 1);
            float hf = (float)(n >> 6);
            float wf = (float)(n & 63);
#pragma unroll
            for (int nf = 0; nf < 4; nf++) {
                float v0 = acc[mf][nf][ri * 2 + 0] + bx[nf];
                float v1 = acc[mf][nf][ri * 2 + 1] + by[nf];
                float f0 = (v0 > 0.f) ? (v0 + 1.f) : __expf(v0);
                float f1 = (v1 > 0.f) ? (v1 + 1.f) : __expf(v1);
                float s, c;
                __sincosf((uh[nf] ? hf : wf) * th[nf], &s, &c);
                float2 fo = make_float2(f0, f1);
                float2 ro = make_float2(c * f0 - s * f1, c * f1 + s * f0);
                size_t off = (size_t)r * CC + jb + nf * 8;
                *(float2*)(feat + off) = fo;
                *(float2*)(rope + off) = ro;
            }
        }
    }
}

// ============================================================================
// K1b/K1c: deterministic two-stage ksum (for kmean)
// ============================================================================
__global__ void k_ksum_part() {
    int b  = blockIdx.y;
    int cx = blockIdx.x;
    int ch = threadIdx.x;
    const float* p = g_kfeat + ((size_t)b * NPOS + cx * 256) * CC + ch;
    float s = 0.f;
    for (int i = 0; i < 256; i++) s += p[(size_t)i * CC];
    g_ksum_part[(b * 16 + cx) * CC + ch] = s;
}

__global__ void k_ksum_final() {
    int idx = blockIdx.x * 256 + threadIdx.x;
    if (idx < BB * CC) {
        int b = idx >> 9, ch = idx & 511;
        float s = 0.f;
        for (int i = 0; i < 16; i++) s += g_ksum_part[(b * 16 + i) * CC + ch];
        g_ksum[idx] = s;
    }
}

// ============================================================================
// K2: kv partials: per (b,head,chunk): 64x64 += k_rope[n,:]^T v[n,:] over 512 n
// ============================================================================
__global__ __launch_bounds__(256) void k_kv_part(const float* __restrict__ x) {
    __shared__ float ks[16 * 64];
    __shared__ float vs[16 * 64];
    int chunk = blockIdx.x;
    int bh    = blockIdx.y;
    int b = bh >> 3, hh = bh & 7;
    int tid = threadIdx.x;
    int ty = tid >> 4, tx = tid & 15;
    int r = tid >> 4, c4 = tid & 15;

    float acc[4][4] = {};
    for (int it = 0; it < 32; ++it) {
        int n0 = chunk * 512 + it * 16;
        size_t gro = ((size_t)b * NPOS + n0 + r) * CC + hh * DH + c4 * 4;
        *(float4*)&ks[r * 64 + c4 * 4] = *(const float4*)(g_krope + gro);
        *(float4*)&vs[r * 64 + c4 * 4] = *(const float4*)(x + gro);
        __syncthreads();
#pragma unroll
        for (int nn = 0; nn < 16; nn++) {
            float4 a  = *(const float4*)&ks[nn * 64 + ty * 4];
            float4 bv = *(const float4*)&vs[nn * 64 + tx * 4];
            float av[4]  = {a.x, a.y, a.z, a.w};
            float bb2[4] = {bv.x, bv.y, bv.z, bv.w};
#pragma unroll
            for (int i = 0; i < 4; i++)
#pragma unroll
                for (int j = 0; j < 4; j++) acc[i][j] += av[i] * bb2[j];
        }
        __syncthreads();
    }
    float* dst = g_kv_part + ((size_t)chunk * 64 + bh) * DH * DH;
#pragma unroll
    for (int i = 0; i < 4; i++)
#pragma unroll
        for (int j = 0; j < 4; j++)
            dst[(ty * 4 + i) * DH + tx * 4 + j] = acc[i][j];
}

__global__ void k_kv_final() {
    int idx = blockIdx.x * 256 + threadIdx.x;
    float s = 0.f;
    for (int c2 = 0; c2 < 8; c2++) s += g_kv_part[(size_t)c2 * 64 * DH * DH + idx];
    g_kv[idx] = s * (1.0f / (float)NPOS);
}

// ============================================================================
// K3: out = (q_rope @ kv) * z + LePE(x)
// ============================================================================
__global__ __launch_bounds__(256) void k_out(const float* __restrict__ x,
                                             const float* __restrict__ lepe_w,
                                             const float* __restrict__ lepe_b,
                                             float* __restrict__ out) {
    __shared__ float s_kv[64 * 68];
    __shared__ float s_qrT[64 * 68];
    __shared__ float s_z[64];
    __shared__ float s_km[64];

    int ntile = blockIdx.x;
    int hh    = blockIdx.y;
    int b     = blockIdx.z;
    int tid   = threadIdx.x;
    int n0    = ntile * 64;

#pragma unroll
    for (int i = 0; i < 4; i++) {
        int f = tid + i * 256;
        int r = f >> 4, c4 = f & 15;
        float4 v = *(const float4*)(g_qfeat + ((size_t)b * NPOS + n0 + r) * CC + hh * DH + c4 * 4);
        *(float4*)&s_kv[r * 68 + c4 * 4] = v;
    }
    if (tid < 64) s_km[tid] = g_ksum[b * CC + hh * DH + tid] * (1.0f / (float)NPOS);
    __syncthreads();

    if (tid < 64) {
        float dot = 0.f;
#pragma unroll
        for (int dd = 0; dd < 64; dd++) dot += s_kv[tid * 68 + dd] * s_km[dd];
        s_z[tid] = 1.0f / (dot + 1e-6f);
    }
    __syncthreads();

#pragma unroll
    for (int i = 0; i < 4; i++) {
        int f = tid + i * 256;
        int r = f >> 4, c4 = f & 15;
        *(float4*)&s_kv[r * 68 + c4 * 4] =
            *(const float4*)(g_kv + ((size_t)(b * NH + hh)) * DH * DH + r * DH + c4 * 4);
        float4 v = *(const float4*)(g_qrope + ((size_t)b * NPOS + n0 + r) * CC + hh * DH + c4 * 4);
        s_qrT[(c4 * 4 + 0) * 68 + r] = v.x;
        s_qrT[(c4 * 4 + 1) * 68 + r] = v.y;
        s_qrT[(c4 * 4 + 2) * 68 + r] = v.z;
        s_qrT[(c4 * 4 + 3) * 68 + r] = v.w;
    }
    __syncthreads();

    int ty = tid >> 4, tx = tid & 15;
    int r0 = ty * 4, e0 = tx * 4;
    float acc[4][4] = {};
#pragma unroll
    for (int dd = 0; dd < 64; dd++) {
        float4 a  = *(const float4*)&s_qrT[dd * 68 + r0];
        float4 bv = *(const float4*)&s_kv[dd * 68 + e0];
        float av[4]  = {a.x, a.y, a.z, a.w};
        float bb2[4] = {bv.x, bv.y, bv.z, bv.w};
#pragma unroll
        for (int i = 0; i < 4; i++)
#pragma unroll
            for (int j = 0; j < 4; j++) acc[i][j] += av[i] * bb2[j];
    }

    const int hi = ntile;
    float wloc[4][9], bloc[4];
#pragma unroll
    for (int j = 0; j < 4; j++) {
        int ch = hh * DH + e0 + j;
        bloc[j] = lepe_b[ch];
#pragma unroll
        for (int q = 0; q < 9; q++) wloc[j][q] = lepe_w[ch * 9 + q];
    }
#pragma unroll
    for (int ri = 0; ri < 4; ri++) {
        int r  = r0 + ri;
        int wi = r;
        int nn = n0 + r;
        float z = s_z[r];
#pragma unroll
        for (int j = 0; j < 4; j++) {
            int ch = hh * DH + e0 + j;
            float pe = bloc[j];
#pragma unroll
            for (int dy = -1; dy <= 1; dy++) {
                int y = hi + dy;
                if ((unsigned)y < 64u) {
#pragma unroll
                    for (int dx = -1; dx <= 1; dx++) {
                        int xw = wi + dx;
                        if ((unsigned)xw < 64u)
                            pe += wloc[j][(dy + 1) * 3 + dx + 1] *
                                  x[((size_t)b * NPOS + y * 64 + xw) * CC + ch];
                    }
                }
            }
            out[((size_t)b * NPOS + nn) * CC + ch] = acc[ri][j] * z + pe;
        }
    }
}

// ============================================================================
extern "C" void kernel_launch(void* const* d_in, const int* in_sizes, int n_in,
                              void* d_out, int out_size) {
    const float *x = nullptr, *Wqk = nullptr, *bqk = nullptr;
    const float *lw = nullptr, *lb = nullptr;
    for (int i = 0; i < n_in; i++) {
        switch (in_sizes[i]) {
            case BB * NPOS * CC: x   = (const float*)d_in[i]; break;
            case 2 * CC * CC:    Wqk = (const float*)d_in[i]; break;
            case 2 * CC:         bqk = (const float*)d_in[i]; break;
            case CC * 9:         lw  = (const float*)d_in[i]; break;
            case CC:             lb  = (const float*)d_in[i]; break;
            default: break;  // h, w scalars
        }
    }
    float* out = (float*)d_out;

    const int GEMM_SMEM = 2 * STG_BYTES;  // 81920
    cudaFuncSetAttribute(k_gemm_mma, cudaFuncAttributeMaxDynamicSharedMemorySize,
                         GEMM_SMEM);

    k_convert<<<(MTOT * 128) / 256, 256>>>(x, 0, MTOT);
    k_convert<<<(NTOT * 128) / 256, 256>>>(Wqk, 1, NTOT);
    k_gemm_mma<<<dim3(8, 256), 256, GEMM_SMEM>>>(bqk);
    k_ksum_part<<<dim3(16, 8), 512>>>();
    k_ksum_final<<<16, 256>>>();
    k_kv_part<<<dim3(8, 64), 256>>>(x);
    k_kv_final<<<1024, 256>>>();
    k_out<<<dim3(64, 8, 8), 256>>>(x, lw, lb, out);
}